// round 14
// baseline (speedup 1.0000x reference)
#include <cuda_runtime.h>
#include <cuda_fp16.h>

#define NNODES 50000
#define INDIM  256
#define D1     128
#define OUTC   40
#define MAXE   800000
#define MAXET  (MAXE + NNODES)

// ---------------- scratch (static device globals; no allocation) ----------------
__device__ __half g_W1h [D1 * INDIM];     // W1^T fp16 [n][k]
__device__ __half g_W2h [OUTC * D1];      // W2^T fp16 [n][k]
__device__ __half g_h1h [NNODES * D1];    // x@W1 fp16 (gather payload)
__device__ __half g_out1h[NNODES * D1];   // elu(agg1+b1) fp16 (gemm2 input)
__device__ __half g_h2h [NNODES * OUTC];
__device__ float  g_als1[NNODES * 4];
__device__ float  g_ald1[NNODES * 4];
__device__ float  g_als2[NNODES];
__device__ float  g_ald2[NNODES];
__device__ int g_deg   [NNODES];
__device__ int g_epos  [MAXE];
__device__ int g_rowptr[NNODES + 1];
__device__ int g_bsum  [256];
__device__ int g_csrsrc[MAXET];

// ---------------- helpers ----------------
__device__ __forceinline__ float lrelu(float x) { return x > 0.f ? x : 0.2f * x; }

__device__ __forceinline__ void gdsync() {
    // waits for PDL predecessor; no-op when not launched as a dependent
    cudaGridDependencySynchronize();
}

__device__ __forceinline__ void mma_f16(float c[4], const unsigned a[4], const unsigned b[2]) {
    asm volatile("mma.sync.aligned.m16n8k16.row.col.f32.f16.f16.f32 "
                 "{%0,%1,%2,%3}, {%4,%5,%6,%7}, {%8,%9}, {%0,%1,%2,%3};"
                 : "+f"(c[0]), "+f"(c[1]), "+f"(c[2]), "+f"(c[3])
                 : "r"(a[0]), "r"(a[1]), "r"(a[2]), "r"(a[3]), "r"(b[0]), "r"(b[1]));
}

__device__ __forceinline__ void cp16(void* smem, const void* gmem) {
    unsigned s = (unsigned)__cvta_generic_to_shared(smem);
    asm volatile("cp.async.cg.shared.global [%0], [%1], 16;" :: "r"(s), "l"(gmem));
}
__device__ __forceinline__ void cpcommit() { asm volatile("cp.async.commit_group;"); }
template<int N> __device__ __forceinline__ void cpwait() {
    asm volatile("cp.async.wait_group %0;" :: "n"(N));
}

__device__ __forceinline__ float pick4(float4 q, int l) {
    float lo = (l & 8)  ? q.y : q.x;
    float hi = (l & 8)  ? q.w : q.z;
    return    (l & 16) ? hi : lo;
}

// ---------------- prep: W transposes (fp16) + deg=0 (self-contained every launch) ----
__global__ __launch_bounds__(256) void k_prep(const float* __restrict__ W1,
                                              const float* __restrict__ W2, int n) {
    int i = blockIdx.x * blockDim.x + threadIdx.x;
    if (i < D1 * INDIM) {
        int nn = i & 127, k = i >> 7;
        g_W1h[nn * INDIM + k] = __float2half(W1[k * D1 + nn]);
    }
    int j = i - D1 * INDIM;
    if (j >= 0 && j < OUTC * D1) {
        int k = j / OUTC, nn = j - k * OUTC;
        g_W2h[nn * D1 + k] = __float2half(W2[k * OUTC + nn]);
    }
    int m = j - OUTC * D1;
    if (m >= 0 && m < n) g_deg[m] = 0;
}

// ---------------- count: per-edge rank via atomic return ----------------
__global__ __launch_bounds__(256) void k_count(const int* __restrict__ ei, int E) {
    int i = blockIdx.x * blockDim.x + threadIdx.x;
    int dst = (i < E) ? __ldg(&ei[E + i]) : 0;   // pure-input prologue
    gdsync();                                    // wait for prep (deg=0)
    if (i < E) g_epos[i] = atomicAdd(&g_deg[dst], 1);
}

// ---------------- scanA: per-block sums of (deg+1) ----------------
__global__ __launch_bounds__(256) void k_scanA(int n) {
    __shared__ int ss[256];
    gdsync();
    int i = blockIdx.x * 256 + threadIdx.x;
    int v = (i < n) ? g_deg[i] + 1 : 0;
    ss[threadIdx.x] = v;
    __syncthreads();
    for (int off = 128; off; off >>= 1) {
        if (threadIdx.x < off) ss[threadIdx.x] += ss[threadIdx.x + off];
        __syncthreads();
    }
    if (threadIdx.x == 0) g_bsum[blockIdx.x] = ss[0];
}

// ---------------- scanC: per-block redundant block-offset scan (no scanB) --------
__global__ __launch_bounds__(256) void k_scanC(int nblk, int n) {
    __shared__ int sb[256];
    __shared__ int ss[256];
    gdsync();
    int t = threadIdx.x;
    int bv = (t < nblk) ? g_bsum[t] : 0;
    sb[t] = bv;
    __syncthreads();
    for (int off = 1; off < 256; off <<= 1) {
        int u = (t >= off) ? sb[t - off] : 0;
        __syncthreads();
        sb[t] += u;
        __syncthreads();
    }
    int blockOff = (blockIdx.x > 0) ? sb[blockIdx.x - 1] : 0;
    if (blockIdx.x == 0 && t == 0) g_rowptr[n] = sb[nblk - 1];
    int i = blockIdx.x * 256 + t;
    int v = (i < n) ? g_deg[i] + 1 : 0;
    ss[t] = v;
    __syncthreads();
    for (int off = 1; off < 256; off <<= 1) {
        int u = (t >= off) ? ss[t - off] : 0;
        __syncthreads();
        ss[t] += u;
        __syncthreads();
    }
    if (i < n) {
        int rp = blockOff + ss[t] - v;
        g_rowptr[i] = rp;
        g_csrsrc[rp] = i;        // self-loop at segment head
    }
}

// ---------------- hybrid: GEMM1 (fp16 mma, pipelined) + atomic-free scatter ------
__global__ __launch_bounds__(256) void k_g1s(const float* __restrict__ x,
                                             const float* __restrict__ a_src,
                                             const float* __restrict__ a_dst,
                                             const int* __restrict__ ei,
                                             int E, int n, int nG1, int nS) {
    __shared__ __half As[2][128 * 40];
    __shared__ __half Bs[2][128 * 40];
    int tid  = threadIdx.x;
    if (blockIdx.x >= nG1) {
        gdsync();                // scatter needs epos + rowptr
        int stride = nS * 256;
        for (int i = (blockIdx.x - nG1) * 256 + tid; i < E; i += stride) {
            int src = __ldg(&ei[i]);
            int dst = __ldg(&ei[E + i]);
            int pos = __ldg(&g_epos[i]);
            g_csrsrc[g_rowptr[dst] + 1 + pos] = src;
        }
        return;
    }
    int lane = tid & 31;
    int wid  = tid >> 5;
    int wm   = wid & 3;
    int wn   = wid >> 2;
    int rowBase = blockIdx.x * 128;
    int gtg  = lane >> 2;
    int tig  = lane & 3;

    float acc[2][8][4];
#pragma unroll
    for (int mi = 0; mi < 2; mi++)
#pragma unroll
        for (int ni = 0; ni < 8; ni++)
#pragma unroll
            for (int j = 0; j < 4; j++) acc[mi][ni][j] = 0.f;

    float4 ar[4];
    auto stageB = [&](int buf, int kt) {
#pragma unroll
        for (int t2 = 0; t2 < 2; t2++) {
            int f = tid + t2 * 256;
            int nn = f >> 2, c = f & 3;
            cp16(&Bs[buf][nn * 40 + c * 8], g_W1h + nn * INDIM + kt * 32 + c * 8);
        }
    };
    auto ldgA = [&](int kt) {
#pragma unroll
        for (int t2 = 0; t2 < 4; t2++) {
            int f = tid + t2 * 256;
            int r = f >> 3, c4 = f & 7;
            int gr = rowBase + r;
            ar[t2] = __ldg((const float4*)(x + (size_t)(gr < n ? gr : 0) * INDIM) + kt * 8 + c4);
        }
    };
    auto stsA = [&](int buf) {
#pragma unroll
        for (int t2 = 0; t2 < 4; t2++) {
            int f = tid + t2 * 256;
            int r = f >> 3, c4 = f & 7;
            __half2 h0 = __floats2half2_rn(ar[t2].x, ar[t2].y);
            __half2 h1 = __floats2half2_rn(ar[t2].z, ar[t2].w);
            uint2 u;
            u.x = *(unsigned*)&h0; u.y = *(unsigned*)&h1;
            *(uint2*)&As[buf][r * 40 + c4 * 4] = u;
        }
    };
    auto compute = [&](int buf) {
#pragma unroll
        for (int kk = 0; kk < 2; kk++) {
            int kb = kk * 16 + 2 * tig;
            unsigned a[2][4], b[8][2];
#pragma unroll
            for (int mi = 0; mi < 2; mi++) {
                int r = wm * 32 + mi * 16 + gtg;
                a[mi][0] = *(unsigned*)&As[buf][r * 40 + kb];
                a[mi][1] = *(unsigned*)&As[buf][(r + 8) * 40 + kb];
                a[mi][2] = *(unsigned*)&As[buf][r * 40 + kb + 8];
                a[mi][3] = *(unsigned*)&As[buf][(r + 8) * 40 + kb + 8];
            }
#pragma unroll
            for (int ni = 0; ni < 8; ni++) {
                int c = wn * 64 + ni * 8 + gtg;
                b[ni][0] = *(unsigned*)&Bs[buf][c * 40 + kb];
                b[ni][1] = *(unsigned*)&Bs[buf][c * 40 + kb + 8];
            }
#pragma unroll
            for (int mi = 0; mi < 2; mi++)
#pragma unroll
                for (int ni = 0; ni < 8; ni++)
                    mma_f16(acc[mi][ni], a[mi], b[ni]);
        }
    };

    // prologue overlap: first A-tile loads depend only on the input x
    ldgA(0);
    gdsync();                    // wait for prep's W1h before staging B
    stageB(0, 0); cpcommit();
    stsA(0);
    stageB(1, 1); cpcommit();
    ldgA(1);
    cpwait<1>();
    __syncthreads();
#pragma unroll
    for (int kt = 0; kt < 8; kt++) {
        if (kt >= 1 && kt < 7) { stageB((kt + 1) & 1, kt + 1); cpcommit(); }
        compute(kt & 1);
        if (kt < 7) {
            stsA((kt + 1) & 1);
            if (kt < 6) ldgA(kt + 2);
            cpwait<0>();
            __syncthreads();
        }
    }
    // epilogue: fp16 store + fused attention-logit dots
    float aS[8][2], aD[8][2];
#pragma unroll
    for (int ni = 0; ni < 8; ni++) {
        int c = wn * 64 + ni * 8 + 2 * tig;
        float2 v = *(const float2*)&a_src[c]; aS[ni][0] = v.x; aS[ni][1] = v.y;
        float2 w = *(const float2*)&a_dst[c]; aD[ni][0] = w.x; aD[ni][1] = w.y;
    }
#pragma unroll
    for (int mi = 0; mi < 2; mi++) {
        int r0 = rowBase + wm * 32 + mi * 16 + gtg;
        float sS[2][2] = {{0.f,0.f},{0.f,0.f}}, sD[2][2] = {{0.f,0.f},{0.f,0.f}};
#pragma unroll
        for (int ni = 0; ni < 8; ni++) {
            int c = wn * 64 + ni * 8 + 2 * tig;
            if (r0 < n)
                *(__half2*)&g_h1h[r0 * D1 + c] = __floats2half2_rn(acc[mi][ni][0], acc[mi][ni][1]);
            if (r0 + 8 < n)
                *(__half2*)&g_h1h[(r0 + 8) * D1 + c] = __floats2half2_rn(acc[mi][ni][2], acc[mi][ni][3]);
            int hd = ni >> 2;
            sS[0][hd] += acc[mi][ni][0]*aS[ni][0] + acc[mi][ni][1]*aS[ni][1];
            sD[0][hd] += acc[mi][ni][0]*aD[ni][0] + acc[mi][ni][1]*aD[ni][1];
            sS[1][hd] += acc[mi][ni][2]*aS[ni][0] + acc[mi][ni][3]*aS[ni][1];
            sD[1][hd] += acc[mi][ni][2]*aD[ni][0] + acc[mi][ni][3]*aD[ni][1];
        }
#pragma unroll
        for (int rr = 0; rr < 2; rr++)
#pragma unroll
            for (int hd = 0; hd < 2; hd++) {
                float s = sS[rr][hd], d = sD[rr][hd];
                s += __shfl_xor_sync(0xffffffffu, s, 1);
                s += __shfl_xor_sync(0xffffffffu, s, 2);
                d += __shfl_xor_sync(0xffffffffu, d, 1);
                d += __shfl_xor_sync(0xffffffffu, d, 2);
                int r = r0 + rr * 8;
                if (tig == 0 && r < n) {
                    g_als1[r * 4 + wn * 2 + hd] = s;
                    g_ald1[r * 4 + wn * 2 + hd] = d;
                }
            }
    }
}

// ---------------- layer-1 aggregation (warp/node, 8-way unroll) + bias + ELU -----
__global__ __launch_bounds__(256) void k_agg1(const float* __restrict__ b1, int n) {
    int node = blockIdx.x * 8 + (threadIdx.x >> 5);
    int l = threadIdx.x & 31;
    float4 b = ((const float4*)b1)[l];       // pure-input prologue
    gdsync();                                // wait for g1s (h1h, logits, csr)
    if (node >= n) return;
    int beg = g_rowptr[node], end = g_rowptr[node + 1];
    float dv = pick4(*((const float4*)g_ald1 + node), l);
    const uint2* hb = (const uint2*)g_h1h;
    float ax = 0.f, ay = 0.f, az = 0.f, aw = 0.f, psum = 0.f;
    int e = beg;
    for (; e + 8 <= end; e += 8) {
        int s[8];
#pragma unroll
        for (int k = 0; k < 8; k++) s[k] = __ldg(&g_csrsrc[e + k]);
        float4 q[8];
#pragma unroll
        for (int k = 0; k < 8; k++) q[k] = __ldg((const float4*)g_als1 + s[k]);
        uint2 u[8];
#pragma unroll
        for (int k = 0; k < 8; k++) u[k] = __ldg(hb + s[k] * 32 + l);
#pragma unroll
        for (int k = 0; k < 8; k++) {
            float p = __expf(lrelu(pick4(q[k], l) + dv));
            float2 fa = __half22float2(*(__half2*)&u[k].x);
            float2 fb = __half22float2(*(__half2*)&u[k].y);
            ax += p * fa.x; ay += p * fa.y; az += p * fb.x; aw += p * fb.y;
            psum += p;
        }
    }
    for (; e < end; e++) {
        int s0 = __ldg(&g_csrsrc[e]);
        float4 q0 = __ldg((const float4*)g_als1 + s0);
        uint2 u0 = __ldg(hb + s0 * 32 + l);
        float p0 = __expf(lrelu(pick4(q0, l) + dv));
        float2 fa = __half22float2(*(__half2*)&u0.x);
        float2 fb = __half22float2(*(__half2*)&u0.y);
        ax += p0*fa.x; ay += p0*fa.y; az += p0*fb.x; aw += p0*fb.y;
        psum += p0;
    }
    float inv = __fdividef(1.f, psum);
    float4 v = make_float4(ax * inv + b.x, ay * inv + b.y, az * inv + b.z, aw * inv + b.w);
    v.x = v.x > 0.f ? v.x : expm1f(v.x);
    v.y = v.y > 0.f ? v.y : expm1f(v.y);
    v.z = v.z > 0.f ? v.z : expm1f(v.z);
    v.w = v.w > 0.f ? v.w : expm1f(v.w);
    __half2 h0 = __floats2half2_rn(v.x, v.y);
    __half2 h1 = __floats2half2_rn(v.z, v.w);
    uint2 u;
    u.x = *(unsigned*)&h0; u.y = *(unsigned*)&h1;
    *(uint2*)&g_out1h[node * D1 + l * 4] = u;
}

// ---------------- GEMM2 (fp16 mma, stage-all-once, fused logits) -----------------
__global__ __launch_bounds__(256) void k_gemm2(const float* __restrict__ a_src,
                                               const float* __restrict__ a_dst, int n) {
    __shared__ __half As2[128 * 136];
    __shared__ __half Bs2[OUTC * 136];
    int tid  = threadIdx.x;
    int lane = tid & 31;
    int wid  = tid >> 5;
    int gtg  = lane >> 2;
    int tig  = lane & 3;
    int rowBase = blockIdx.x * 128;

    // pure-input prologue: logit vectors
    float aS[5][2], aD[5][2];
#pragma unroll
    for (int ni = 0; ni < 5; ni++) {
        int c = ni * 8 + 2 * tig;
        float2 v = *(const float2*)&a_src[c]; aS[ni][0] = v.x; aS[ni][1] = v.y;
        float2 w = *(const float2*)&a_dst[c]; aD[ni][0] = w.x; aD[ni][1] = w.y;
    }
    gdsync();                                // wait for agg1 (out1h)

#pragma unroll
    for (int t2 = 0; t2 < 8; t2++) {
        int f = tid + t2 * 256;
        int r = f >> 4, c = f & 15;
        int gr = rowBase + r;
        cp16(&As2[r * 136 + c * 8], g_out1h + (size_t)(gr < n ? gr : 0) * D1 + c * 8);
    }
    for (int f = tid; f < OUTC * 16; f += 256) {
        int r = f >> 4, c = f & 15;
        cp16(&Bs2[r * 136 + c * 8], g_W2h + r * D1 + c * 8);
    }
    cpcommit(); cpwait<0>();
    __syncthreads();

    float acc[5][4];
#pragma unroll
    for (int ni = 0; ni < 5; ni++)
#pragma unroll
        for (int j = 0; j < 4; j++) acc[ni][j] = 0.f;

#pragma unroll
    for (int kk = 0; kk < 8; kk++) {
        int kb = kk * 16 + 2 * tig;
        unsigned a[4], b[5][2];
        int r = wid * 16 + gtg;
        a[0] = *(unsigned*)&As2[r * 136 + kb];
        a[1] = *(unsigned*)&As2[(r + 8) * 136 + kb];
        a[2] = *(unsigned*)&As2[r * 136 + kb + 8];
        a[3] = *(unsigned*)&As2[(r + 8) * 136 + kb + 8];
#pragma unroll
        for (int ni = 0; ni < 5; ni++) {
            int c = ni * 8 + gtg;
            b[ni][0] = *(unsigned*)&Bs2[c * 136 + kb];
            b[ni][1] = *(unsigned*)&Bs2[c * 136 + kb + 8];
        }
#pragma unroll
        for (int ni = 0; ni < 5; ni++)
            mma_f16(acc[ni], a, b[ni]);
    }
    int r0 = rowBase + wid * 16 + gtg;
    float sS[2] = {0.f, 0.f}, sD[2] = {0.f, 0.f};
#pragma unroll
    for (int ni = 0; ni < 5; ni++) {
        int c = ni * 8 + 2 * tig;
        if (r0 < n)
            *(__half2*)&g_h2h[r0 * OUTC + c] = __floats2half2_rn(acc[ni][0], acc[ni][1]);
        if (r0 + 8 < n)
            *(__half2*)&g_h2h[(r0 + 8) * OUTC + c] = __floats2half2_rn(acc[ni][2], acc[ni][3]);
        sS[0] += acc[ni][0]*aS[ni][0] + acc[ni][1]*aS[ni][1];
        sD[0] += acc[ni][0]*aD[ni][0] + acc[ni][1]*aD[ni][1];
        sS[1] += acc[ni][2]*aS[ni][0] + acc[ni][3]*aS[ni][1];
        sD[1] += acc[ni][2]*aD[ni][0] + acc[ni][3]*aD[ni][1];
    }
#pragma unroll
    for (int rr = 0; rr < 2; rr++) {
        float s = sS[rr], d = sD[rr];
        s += __shfl_xor_sync(0xffffffffu, s, 1);
        s += __shfl_xor_sync(0xffffffffu, s, 2);
        d += __shfl_xor_sync(0xffffffffu, d, 1);
        d += __shfl_xor_sync(0xffffffffu, d, 2);
        int r = r0 + rr * 8;
        if (tig == 0 && r < n) { g_als2[r] = s; g_ald2[r] = d; }
    }
}

// ---------------- layer-2 aggregation + bias + log_softmax (warp/node, 4-way) ----
__global__ __launch_bounds__(256) void k_agg2(float* __restrict__ out,
                                              const float* __restrict__ b2, int n) {
    int node = blockIdx.x * 8 + (threadIdx.x >> 5);
    int l = threadIdx.x & 31;
    bool act = (l < 20);
    float2 bb = act ? *(const float2*)&b2[2 * l] : make_float2(0.f, 0.f);  // input prologue
    gdsync();                                // wait for gemm2 (h2h, logits)
    if (node >= n) return;
    int beg = g_rowptr[node], end = g_rowptr[node + 1];
    float dv = g_ald2[node];
    float aa = 0.f, ab = 0.f, psum = 0.f;
    int e = beg;
    for (; e + 4 <= end; e += 4) {
        int s[4];
#pragma unroll
        for (int k = 0; k < 4; k++) s[k] = __ldg(&g_csrsrc[e + k]);
        float v[4];
#pragma unroll
        for (int k = 0; k < 4; k++) v[k] = __ldg(&g_als2[s[k]]);
        float2 f[4];
#pragma unroll
        for (int k = 0; k < 4; k++)
            f[k] = act ? __half22float2(__ldg((const __half2*)(g_h2h + s[k] * OUTC) + l))
                       : make_float2(0.f, 0.f);
#pragma unroll
        for (int k = 0; k < 4; k++) {
            float p = __expf(lrelu(v[k] + dv));
            aa += p * f[k].x;
            ab += p * f[k].y;
            psum += p;
        }
    }
    for (; e < end; e++) {
        int s0 = __ldg(&g_csrsrc[e]);
        float v0 = __ldg(&g_als2[s0]);
        float p0 = __expf(lrelu(v0 + dv));
        if (act) {
            float2 f0 = __half22float2(__ldg((const __half2*)(g_h2h + s0 * OUTC) + l));
            aa += p0 * f0.x;
            ab += p0 * f0.y;
        }
        psum += p0;
    }
    float inv = __fdividef(1.f, psum);
    float a = __int_as_float(0xff800000), b = __int_as_float(0xff800000);
    if (act) {
        a = aa * inv + bb.x;
        b = ab * inv + bb.y;
    }
    float mx = fmaxf(a, b);
#pragma unroll
    for (int o = 16; o; o >>= 1) mx = fmaxf(mx, __shfl_xor_sync(0xffffffffu, mx, o));
    float se = act ? (__expf(a - mx) + __expf(b - mx)) : 0.f;
#pragma unroll
    for (int o = 16; o; o >>= 1) se += __shfl_xor_sync(0xffffffffu, se, o);
    float lse = logf(se);
    if (act) {
        out[node * OUTC + 2 * l]     = a - mx - lse;
        out[node * OUTC + 2 * l + 1] = b - mx - lse;
    }
}

// ---------------- launch (all kernels chained with PDL) ----------------
static inline int cdiv(int a, int b) { return (a + b - 1) / b; }

template <typename F, typename... Args>
static void launch_pdl(F f, int grid, Args... args) {
    cudaLaunchAttribute at[1];
    at[0].id = cudaLaunchAttributeProgrammaticStreamSerialization;
    at[0].val.programmaticStreamSerializationAllowed = 1;
    cudaLaunchConfig_t cfg = {};
    cfg.gridDim = dim3((unsigned)grid, 1, 1);
    cfg.blockDim = dim3(256, 1, 1);
    cfg.dynamicSmemBytes = 0;
    cfg.stream = 0;
    cfg.attrs = at;
    cfg.numAttrs = 1;
    cudaLaunchKernelEx(&cfg, f, args...);
}

extern "C" void kernel_launch(void* const* d_in, const int* in_sizes, int n_in,
                              void* d_out, int out_size) {
    const float* x      = (const float*)d_in[0];
    const int*   ei     = (const int*)  d_in[1];
    const float* W1     = (const float*)d_in[2];
    const float* a_src1 = (const float*)d_in[3];
    const float* a_dst1 = (const float*)d_in[4];
    const float* b1     = (const float*)d_in[5];
    const float* W2     = (const float*)d_in[6];
    const float* a_src2 = (const float*)d_in[7];
    const float* a_dst2 = (const float*)d_in[8];
    const float* b2     = (const float*)d_in[9];
    float* out = (float*)d_out;

    const int n  = NNODES;
    const int E  = in_sizes[1] / 2;
    const int nG1 = cdiv(n, 128);
    const int nS  = 592;
    const int nblk = cdiv(n, 256);

    const int prepW = D1 * INDIM + OUTC * D1 + n;
    launch_pdl(k_prep,  cdiv(prepW, 256), W1, W2, n);
    launch_pdl(k_count, cdiv(E, 256), ei, E);
    launch_pdl(k_scanA, nblk, n);
    launch_pdl(k_scanC, nblk, nblk, n);
    launch_pdl(k_g1s,   nG1 + nS, x, a_src1, a_dst1, ei, E, n, nG1, nS);
    launch_pdl(k_agg1,  cdiv(n, 8), b1, n);
    launch_pdl(k_gemm2, cdiv(n, 128), a_src2, a_dst2, n);
    launch_pdl(k_agg2,  cdiv(n, 8), out, b2, n);
}

// round 15
// speedup vs baseline: 1.1567x; 1.1567x over previous
#include <cuda_runtime.h>
#include <cuda_fp16.h>

#define NNODES 50000
#define INDIM  256
#define D1     128
#define OUTC   40
#define MAXE   800000
#define MAXET  (MAXE + NNODES)

// ---------------- scratch (static device globals; no allocation) ----------------
__device__ __half g_W1h [D1 * INDIM];     // W1^T fp16 [n][k]
__device__ __half g_W2h [OUTC * D1];      // W2^T fp16 [n][k]
__device__ __half g_h1h [NNODES * D1];    // x@W1 fp16 (gather payload)
__device__ __half g_out1h[NNODES * D1];   // elu(agg1+b1) fp16 (gemm2 input)
__device__ __half g_h2h [NNODES * OUTC];
__device__ float  g_als1[NNODES * 4];
__device__ float  g_ald1[NNODES * 4];
__device__ float  g_als2[NNODES];
__device__ float  g_ald2[NNODES];
__device__ int g_deg   [NNODES];
__device__ int g_epos  [MAXE];
__device__ int g_rowptr[NNODES + 1];
__device__ int g_bsum  [256];
__device__ int g_csrsrc[MAXET];

// ---------------- helpers ----------------
__device__ __forceinline__ float lrelu(float x) { return x > 0.f ? x : 0.2f * x; }

__device__ __forceinline__ void mma_f16(float c[4], const unsigned a[4], const unsigned b[2]) {
    asm volatile("mma.sync.aligned.m16n8k16.row.col.f32.f16.f16.f32 "
                 "{%0,%1,%2,%3}, {%4,%5,%6,%7}, {%8,%9}, {%0,%1,%2,%3};"
                 : "+f"(c[0]), "+f"(c[1]), "+f"(c[2]), "+f"(c[3])
                 : "r"(a[0]), "r"(a[1]), "r"(a[2]), "r"(a[3]), "r"(b[0]), "r"(b[1]));
}

__device__ __forceinline__ void cp16(void* smem, const void* gmem) {
    unsigned s = (unsigned)__cvta_generic_to_shared(smem);
    asm volatile("cp.async.cg.shared.global [%0], [%1], 16;" :: "r"(s), "l"(gmem));
}
__device__ __forceinline__ void cpcommit() { asm volatile("cp.async.commit_group;"); }
template<int N> __device__ __forceinline__ void cpwait() {
    asm volatile("cp.async.wait_group %0;" :: "n"(N));
}

__device__ __forceinline__ float pick4(float4 q, int l) {
    float lo = (l & 8)  ? q.y : q.x;
    float hi = (l & 8)  ? q.w : q.z;
    return    (l & 16) ? hi : lo;
}

// ---------------- prep: W transposes (fp16) + deg=0 (self-contained every launch) ----
__global__ __launch_bounds__(256) void k_prep(const float* __restrict__ W1,
                                              const float* __restrict__ W2, int n) {
    int i = blockIdx.x * blockDim.x + threadIdx.x;
    if (i < D1 * INDIM) {
        int nn = i & 127, k = i >> 7;
        g_W1h[nn * INDIM + k] = __float2half(W1[k * D1 + nn]);
    }
    int j = i - D1 * INDIM;
    if (j >= 0 && j < OUTC * D1) {
        int k = j / OUTC, nn = j - k * OUTC;
        g_W2h[nn * D1 + k] = __float2half(W2[k * OUTC + nn]);
    }
    int m = j - OUTC * D1;
    if (m >= 0 && m < n) g_deg[m] = 0;
}

// ---------------- count: per-edge rank via atomic return ----------------
__global__ __launch_bounds__(256) void k_count(const int* __restrict__ ei, int E) {
    int i = blockIdx.x * blockDim.x + threadIdx.x;
    if (i < E) g_epos[i] = atomicAdd(&g_deg[ei[E + i]], 1);
}

// ---------------- scanA: per-block sums of (deg+1) ----------------
__global__ __launch_bounds__(256) void k_scanA(int n) {
    __shared__ int ss[256];
    int i = blockIdx.x * 256 + threadIdx.x;
    int v = (i < n) ? g_deg[i] + 1 : 0;
    ss[threadIdx.x] = v;
    __syncthreads();
    for (int off = 128; off; off >>= 1) {
        if (threadIdx.x < off) ss[threadIdx.x] += ss[threadIdx.x + off];
        __syncthreads();
    }
    if (threadIdx.x == 0) g_bsum[blockIdx.x] = ss[0];
}

// ---------------- scanC: per-block redundant block-offset scan (no scanB) --------
__global__ __launch_bounds__(256) void k_scanC(int nblk, int n) {
    __shared__ int sb[256];
    __shared__ int ss[256];
    int t = threadIdx.x;
    int bv = (t < nblk) ? g_bsum[t] : 0;
    sb[t] = bv;
    __syncthreads();
    for (int off = 1; off < 256; off <<= 1) {
        int u = (t >= off) ? sb[t - off] : 0;
        __syncthreads();
        sb[t] += u;
        __syncthreads();
    }
    int blockOff = (blockIdx.x > 0) ? sb[blockIdx.x - 1] : 0;
    if (blockIdx.x == 0 && t == 0) g_rowptr[n] = sb[nblk - 1];
    int i = blockIdx.x * 256 + t;
    int v = (i < n) ? g_deg[i] + 1 : 0;
    ss[t] = v;
    __syncthreads();
    for (int off = 1; off < 256; off <<= 1) {
        int u = (t >= off) ? ss[t - off] : 0;
        __syncthreads();
        ss[t] += u;
        __syncthreads();
    }
    if (i < n) {
        int rp = blockOff + ss[t] - v;
        g_rowptr[i] = rp;
        g_csrsrc[rp] = i;        // self-loop at segment head
    }
}

// ---------------- scatter: atomic-free CSR fill (side stream) ----------------
__global__ __launch_bounds__(256) void k_scatter(const int* __restrict__ ei, int E) {
    int i = blockIdx.x * 256 + threadIdx.x;
    if (i < E) {
        int src = __ldg(&ei[i]);
        int dst = __ldg(&ei[E + i]);
        int pos = __ldg(&g_epos[i]);
        g_csrsrc[g_rowptr[dst] + 1 + pos] = src;
    }
}

// ---------------- GEMM1 (fp16 mma, pipelined, fused logits, fp16 out) ------------
__global__ __launch_bounds__(256) void k_gemm1(const float* __restrict__ x,
                                               const float* __restrict__ a_src,
                                               const float* __restrict__ a_dst, int n) {
    __shared__ __half As[2][128 * 40];
    __shared__ __half Bs[2][128 * 40];
    int tid  = threadIdx.x;
    int lane = tid & 31;
    int wid  = tid >> 5;
    int wm   = wid & 3;
    int wn   = wid >> 2;
    int rowBase = blockIdx.x * 128;
    int gtg  = lane >> 2;
    int tig  = lane & 3;

    float acc[2][8][4];
#pragma unroll
    for (int mi = 0; mi < 2; mi++)
#pragma unroll
        for (int ni = 0; ni < 8; ni++)
#pragma unroll
            for (int j = 0; j < 4; j++) acc[mi][ni][j] = 0.f;

    float4 ar[4];
    auto stageB = [&](int buf, int kt) {
#pragma unroll
        for (int t2 = 0; t2 < 2; t2++) {
            int f = tid + t2 * 256;
            int nn = f >> 2, c = f & 3;
            cp16(&Bs[buf][nn * 40 + c * 8], g_W1h + nn * INDIM + kt * 32 + c * 8);
        }
    };
    auto ldgA = [&](int kt) {
#pragma unroll
        for (int t2 = 0; t2 < 4; t2++) {
            int f = tid + t2 * 256;
            int r = f >> 3, c4 = f & 7;
            int gr = rowBase + r;
            ar[t2] = __ldg((const float4*)(x + (size_t)(gr < n ? gr : 0) * INDIM) + kt * 8 + c4);
        }
    };
    auto stsA = [&](int buf) {
#pragma unroll
        for (int t2 = 0; t2 < 4; t2++) {
            int f = tid + t2 * 256;
            int r = f >> 3, c4 = f & 7;
            __half2 h0 = __floats2half2_rn(ar[t2].x, ar[t2].y);
            __half2 h1 = __floats2half2_rn(ar[t2].z, ar[t2].w);
            uint2 u;
            u.x = *(unsigned*)&h0; u.y = *(unsigned*)&h1;
            *(uint2*)&As[buf][r * 40 + c4 * 4] = u;
        }
    };
    auto compute = [&](int buf) {
#pragma unroll
        for (int kk = 0; kk < 2; kk++) {
            int kb = kk * 16 + 2 * tig;
            unsigned a[2][4], b[8][2];
#pragma unroll
            for (int mi = 0; mi < 2; mi++) {
                int r = wm * 32 + mi * 16 + gtg;
                a[mi][0] = *(unsigned*)&As[buf][r * 40 + kb];
                a[mi][1] = *(unsigned*)&As[buf][(r + 8) * 40 + kb];
                a[mi][2] = *(unsigned*)&As[buf][r * 40 + kb + 8];
                a[mi][3] = *(unsigned*)&As[buf][(r + 8) * 40 + kb + 8];
            }
#pragma unroll
            for (int ni = 0; ni < 8; ni++) {
                int c = wn * 64 + ni * 8 + gtg;
                b[ni][0] = *(unsigned*)&Bs[buf][c * 40 + kb];
                b[ni][1] = *(unsigned*)&Bs[buf][c * 40 + kb + 8];
            }
#pragma unroll
            for (int mi = 0; mi < 2; mi++)
#pragma unroll
                for (int ni = 0; ni < 8; ni++)
                    mma_f16(acc[mi][ni], a[mi], b[ni]);
        }
    };

    stageB(0, 0); cpcommit();
    ldgA(0); stsA(0);
    stageB(1, 1); cpcommit();
    ldgA(1);
    cpwait<1>();
    __syncthreads();
#pragma unroll
    for (int kt = 0; kt < 8; kt++) {
        if (kt >= 1 && kt < 7) { stageB((kt + 1) & 1, kt + 1); cpcommit(); }
        compute(kt & 1);
        if (kt < 7) {
            stsA((kt + 1) & 1);
            if (kt < 6) ldgA(kt + 2);
            cpwait<0>();
            __syncthreads();
        }
    }
    // epilogue: fp16 store + fused attention-logit dots
    float aS[8][2], aD[8][2];
#pragma unroll
    for (int ni = 0; ni < 8; ni++) {
        int c = wn * 64 + ni * 8 + 2 * tig;
        float2 v = *(const float2*)&a_src[c]; aS[ni][0] = v.x; aS[ni][1] = v.y;
        float2 w = *(const float2*)&a_dst[c]; aD[ni][0] = w.x; aD[ni][1] = w.y;
    }
#pragma unroll
    for (int mi = 0; mi < 2; mi++) {
        int r0 = rowBase + wm * 32 + mi * 16 + gtg;
        float sS[2][2] = {{0.f,0.f},{0.f,0.f}}, sD[2][2] = {{0.f,0.f},{0.f,0.f}};
#pragma unroll
        for (int ni = 0; ni < 8; ni++) {
            int c = wn * 64 + ni * 8 + 2 * tig;
            if (r0 < n)
                *(__half2*)&g_h1h[r0 * D1 + c] = __floats2half2_rn(acc[mi][ni][0], acc[mi][ni][1]);
            if (r0 + 8 < n)
                *(__half2*)&g_h1h[(r0 + 8) * D1 + c] = __floats2half2_rn(acc[mi][ni][2], acc[mi][ni][3]);
            int hd = ni >> 2;
            sS[0][hd] += acc[mi][ni][0]*aS[ni][0] + acc[mi][ni][1]*aS[ni][1];
            sD[0][hd] += acc[mi][ni][0]*aD[ni][0] + acc[mi][ni][1]*aD[ni][1];
            sS[1][hd] += acc[mi][ni][2]*aS[ni][0] + acc[mi][ni][3]*aS[ni][1];
            sD[1][hd] += acc[mi][ni][2]*aD[ni][0] + acc[mi][ni][3]*aD[ni][1];
        }
#pragma unroll
        for (int rr = 0; rr < 2; rr++)
#pragma unroll
            for (int hd = 0; hd < 2; hd++) {
                float s = sS[rr][hd], d = sD[rr][hd];
                s += __shfl_xor_sync(0xffffffffu, s, 1);
                s += __shfl_xor_sync(0xffffffffu, s, 2);
                d += __shfl_xor_sync(0xffffffffu, d, 1);
                d += __shfl_xor_sync(0xffffffffu, d, 2);
                int r = r0 + rr * 8;
                if (tig == 0 && r < n) {
                    g_als1[r * 4 + wn * 2 + hd] = s;
                    g_ald1[r * 4 + wn * 2 + hd] = d;
                }
            }
    }
}

// ---------------- layer-1 aggregation (warp/node, 8-way unroll) + bias + ELU -----
__global__ __launch_bounds__(256) void k_agg1(const float* __restrict__ b1, int n) {
    int node = blockIdx.x * 8 + (threadIdx.x >> 5);
    if (node >= n) return;
    int l = threadIdx.x & 31;
    int beg = g_rowptr[node], end = g_rowptr[node + 1];
    float dv = pick4(*((const float4*)g_ald1 + node), l);
    const uint2* hb = (const uint2*)g_h1h;
    float ax = 0.f, ay = 0.f, az = 0.f, aw = 0.f, psum = 0.f;
    int e = beg;
    for (; e + 8 <= end; e += 8) {
        int s[8];
#pragma unroll
        for (int k = 0; k < 8; k++) s[k] = __ldg(&g_csrsrc[e + k]);
        float4 q[8];
#pragma unroll
        for (int k = 0; k < 8; k++) q[k] = __ldg((const float4*)g_als1 + s[k]);
        uint2 u[8];
#pragma unroll
        for (int k = 0; k < 8; k++) u[k] = __ldg(hb + s[k] * 32 + l);
#pragma unroll
        for (int k = 0; k < 8; k++) {
            float p = __expf(lrelu(pick4(q[k], l) + dv));
            float2 fa = __half22float2(*(__half2*)&u[k].x);
            float2 fb = __half22float2(*(__half2*)&u[k].y);
            ax += p * fa.x; ay += p * fa.y; az += p * fb.x; aw += p * fb.y;
            psum += p;
        }
    }
    for (; e < end; e++) {
        int s0 = __ldg(&g_csrsrc[e]);
        float4 q0 = __ldg((const float4*)g_als1 + s0);
        uint2 u0 = __ldg(hb + s0 * 32 + l);
        float p0 = __expf(lrelu(pick4(q0, l) + dv));
        float2 fa = __half22float2(*(__half2*)&u0.x);
        float2 fb = __half22float2(*(__half2*)&u0.y);
        ax += p0*fa.x; ay += p0*fa.y; az += p0*fb.x; aw += p0*fb.y;
        psum += p0;
    }
    float inv = __fdividef(1.f, psum);
    float4 b = ((const float4*)b1)[l];
    float4 v = make_float4(ax * inv + b.x, ay * inv + b.y, az * inv + b.z, aw * inv + b.w);
    v.x = v.x > 0.f ? v.x : expm1f(v.x);
    v.y = v.y > 0.f ? v.y : expm1f(v.y);
    v.z = v.z > 0.f ? v.z : expm1f(v.z);
    v.w = v.w > 0.f ? v.w : expm1f(v.w);
    __half2 h0 = __floats2half2_rn(v.x, v.y);
    __half2 h1 = __floats2half2_rn(v.z, v.w);
    uint2 u;
    u.x = *(unsigned*)&h0; u.y = *(unsigned*)&h1;
    *(uint2*)&g_out1h[node * D1 + l * 4] = u;
}

// ---------------- GEMM2 (fp16 mma, stage-all-once, fused logits) -----------------
__global__ __launch_bounds__(256) void k_gemm2(const float* __restrict__ a_src,
                                               const float* __restrict__ a_dst, int n) {
    __shared__ __half As2[128 * 136];
    __shared__ __half Bs2[OUTC * 136];
    int tid  = threadIdx.x;
    int lane = tid & 31;
    int wid  = tid >> 5;
    int gtg  = lane >> 2;
    int tig  = lane & 3;
    int rowBase = blockIdx.x * 128;

#pragma unroll
    for (int t2 = 0; t2 < 8; t2++) {
        int f = tid + t2 * 256;
        int r = f >> 4, c = f & 15;
        int gr = rowBase + r;
        cp16(&As2[r * 136 + c * 8], g_out1h + (size_t)(gr < n ? gr : 0) * D1 + c * 8);
    }
    for (int f = tid; f < OUTC * 16; f += 256) {
        int r = f >> 4, c = f & 15;
        cp16(&Bs2[r * 136 + c * 8], g_W2h + r * D1 + c * 8);
    }
    cpcommit(); cpwait<0>();
    __syncthreads();

    float acc[5][4];
#pragma unroll
    for (int ni = 0; ni < 5; ni++)
#pragma unroll
        for (int j = 0; j < 4; j++) acc[ni][j] = 0.f;

#pragma unroll
    for (int kk = 0; kk < 8; kk++) {
        int kb = kk * 16 + 2 * tig;
        unsigned a[4], b[5][2];
        int r = wid * 16 + gtg;
        a[0] = *(unsigned*)&As2[r * 136 + kb];
        a[1] = *(unsigned*)&As2[(r + 8) * 136 + kb];
        a[2] = *(unsigned*)&As2[r * 136 + kb + 8];
        a[3] = *(unsigned*)&As2[(r + 8) * 136 + kb + 8];
#pragma unroll
        for (int ni = 0; ni < 5; ni++) {
            int c = ni * 8 + gtg;
            b[ni][0] = *(unsigned*)&Bs2[c * 136 + kb];
            b[ni][1] = *(unsigned*)&Bs2[c * 136 + kb + 8];
        }
#pragma unroll
        for (int ni = 0; ni < 5; ni++)
            mma_f16(acc[ni], a, b[ni]);
    }
    int r0 = rowBase + wid * 16 + gtg;
    float aS[5][2], aD[5][2];
#pragma unroll
    for (int ni = 0; ni < 5; ni++) {
        int c = ni * 8 + 2 * tig;
        float2 v = *(const float2*)&a_src[c]; aS[ni][0] = v.x; aS[ni][1] = v.y;
        float2 w = *(const float2*)&a_dst[c]; aD[ni][0] = w.x; aD[ni][1] = w.y;
    }
    float sS[2] = {0.f, 0.f}, sD[2] = {0.f, 0.f};
#pragma unroll
    for (int ni = 0; ni < 5; ni++) {
        int c = ni * 8 + 2 * tig;
        if (r0 < n)
            *(__half2*)&g_h2h[r0 * OUTC + c] = __floats2half2_rn(acc[ni][0], acc[ni][1]);
        if (r0 + 8 < n)
            *(__half2*)&g_h2h[(r0 + 8) * OUTC + c] = __floats2half2_rn(acc[ni][2], acc[ni][3]);
        sS[0] += acc[ni][0]*aS[ni][0] + acc[ni][1]*aS[ni][1];
        sD[0] += acc[ni][0]*aD[ni][0] + acc[ni][1]*aD[ni][1];
        sS[1] += acc[ni][2]*aS[ni][0] + acc[ni][3]*aS[ni][1];
        sD[1] += acc[ni][2]*aD[ni][0] + acc[ni][3]*aD[ni][1];
    }
#pragma unroll
    for (int rr = 0; rr < 2; rr++) {
        float s = sS[rr], d = sD[rr];
        s += __shfl_xor_sync(0xffffffffu, s, 1);
        s += __shfl_xor_sync(0xffffffffu, s, 2);
        d += __shfl_xor_sync(0xffffffffu, d, 1);
        d += __shfl_xor_sync(0xffffffffu, d, 2);
        int r = r0 + rr * 8;
        if (tig == 0 && r < n) { g_als2[r] = s; g_ald2[r] = d; }
    }
}

// ---------------- layer-2 aggregation + bias + log_softmax (warp/node, 4-way) ----
__global__ __launch_bounds__(256) void k_agg2(float* __restrict__ out,
                                              const float* __restrict__ b2, int n) {
    int node = blockIdx.x * 8 + (threadIdx.x >> 5);
    if (node >= n) return;
    int l = threadIdx.x & 31;
    bool act = (l < 20);
    int beg = g_rowptr[node], end = g_rowptr[node + 1];
    float dv = g_ald2[node];
    float aa = 0.f, ab = 0.f, psum = 0.f;
    int e = beg;
    for (; e + 4 <= end; e += 4) {
        int s[4];
#pragma unroll
        for (int k = 0; k < 4; k++) s[k] = __ldg(&g_csrsrc[e + k]);
        float v[4];
#pragma unroll
        for (int k = 0; k < 4; k++) v[k] = __ldg(&g_als2[s[k]]);
        float2 f[4];
#pragma unroll
        for (int k = 0; k < 4; k++)
            f[k] = act ? __half22float2(__ldg((const __half2*)(g_h2h + s[k] * OUTC) + l))
                       : make_float2(0.f, 0.f);
#pragma unroll
        for (int k = 0; k < 4; k++) {
            float p = __expf(lrelu(v[k] + dv));
            aa += p * f[k].x;
            ab += p * f[k].y;
            psum += p;
        }
    }
    for (; e < end; e++) {
        int s0 = __ldg(&g_csrsrc[e]);
        float v0 = __ldg(&g_als2[s0]);
        float p0 = __expf(lrelu(v0 + dv));
        if (act) {
            float2 f0 = __half22float2(__ldg((const __half2*)(g_h2h + s0 * OUTC) + l));
            aa += p0 * f0.x;
            ab += p0 * f0.y;
        }
        psum += p0;
    }
    float inv = __fdividef(1.f, psum);
    float a = __int_as_float(0xff800000), b = __int_as_float(0xff800000);
    if (act) {
        float2 bb = *(const float2*)&b2[2 * l];
        a = aa * inv + bb.x;
        b = ab * inv + bb.y;
    }
    float mx = fmaxf(a, b);
#pragma unroll
    for (int o = 16; o; o >>= 1) mx = fmaxf(mx, __shfl_xor_sync(0xffffffffu, mx, o));
    float se = act ? (__expf(a - mx) + __expf(b - mx)) : 0.f;
#pragma unroll
    for (int o = 16; o; o >>= 1) se += __shfl_xor_sync(0xffffffffu, se, o);
    float lse = logf(se);
    if (act) {
        out[node * OUTC + 2 * l]     = a - mx - lse;
        out[node * OUTC + 2 * l + 1] = b - mx - lse;
    }
}

// ---------------- launch: forked-stream graph (GEMM1 || CSR chain) ----------------
static inline int cdiv(int a, int b) { return (a + b - 1) / b; }

extern "C" void kernel_launch(void* const* d_in, const int* in_sizes, int n_in,
                              void* d_out, int out_size) {
    const float* x      = (const float*)d_in[0];
    const int*   ei     = (const int*)  d_in[1];
    const float* W1     = (const float*)d_in[2];
    const float* a_src1 = (const float*)d_in[3];
    const float* a_dst1 = (const float*)d_in[4];
    const float* b1     = (const float*)d_in[5];
    const float* W2     = (const float*)d_in[6];
    const float* a_src2 = (const float*)d_in[7];
    const float* a_dst2 = (const float*)d_in[8];
    const float* b2     = (const float*)d_in[9];
    float* out = (float*)d_out;

    const int n  = NNODES;
    const int E  = in_sizes[1] / 2;
    const int nG1 = cdiv(n, 128);
    const int nblk = cdiv(n, 256);

    // one-time side stream + events (created on first, uncaptured, call)
    static cudaStream_t s2 = nullptr;
    static cudaEvent_t evFork = nullptr, evJoin = nullptr;
    if (s2 == nullptr) {
        cudaStreamCreateWithFlags(&s2, cudaStreamNonBlocking);
        cudaEventCreateWithFlags(&evFork, cudaEventDisableTiming);
        cudaEventCreateWithFlags(&evJoin, cudaEventDisableTiming);
    }

    const int prepW = D1 * INDIM + OUTC * D1 + n;
    k_prep<<<cdiv(prepW, 256), 256>>>(W1, W2, n);

    // fork: CSR chain on side stream, GEMM1 on main stream
    cudaEventRecord(evFork, 0);
    cudaStreamWaitEvent(s2, evFork, 0);

    k_count  <<<cdiv(E, 256), 256, 0, s2>>>(ei, E);
    k_scanA  <<<nblk, 256, 0, s2>>>(n);
    k_scanC  <<<nblk, 256, 0, s2>>>(nblk, n);
    k_scatter<<<cdiv(E, 256), 256, 0, s2>>>(ei, E);
    cudaEventRecord(evJoin, s2);

    k_gemm1<<<nG1, 256>>>(x, a_src1, a_dst1, n);

    // join: agg1 needs both branches
    cudaStreamWaitEvent(0, evJoin, 0);
    k_agg1 <<<cdiv(n, 8), 256>>>(b1, n);
    k_gemm2<<<cdiv(n, 128), 256>>>(a_src2, a_dst2, n);
    k_agg2 <<<cdiv(n, 8), 256>>>(out, b2, n);
}